// round 13
// baseline (speedup 1.0000x reference)
#include <cuda_runtime.h>
#include <cuda_bf16.h>
#include <cstdint>

#define B_   128
#define S_   1024
#define I_   128
#define H_   256
#define OFF_SLOPE 0.001f
#define HPITCH 132
#define XPITCH 66
#define TXBYTES 8192u

__device__ __forceinline__ void split_pack(float x, float y,
                                           uint32_t& hi, uint32_t& lo) {
    __nv_bfloat16 hx = __float2bfloat16(x);
    __nv_bfloat16 hy = __float2bfloat16(y);
    __nv_bfloat16 lx = __float2bfloat16(x - __bfloat162float(hx));
    __nv_bfloat16 ly = __float2bfloat16(y - __bfloat162float(hy));
    hi = (uint32_t)__bfloat16_as_ushort(hx) | ((uint32_t)__bfloat16_as_ushort(hy) << 16);
    lo = (uint32_t)__bfloat16_as_ushort(lx) | ((uint32_t)__bfloat16_as_ushort(ly) << 16);
}

__device__ __forceinline__ void mma_bf16(float4& d, const uint32_t* a,
                                         uint32_t b0, uint32_t b1) {
    asm volatile(
        "mma.sync.aligned.m16n8k16.row.col.f32.bf16.bf16.f32 "
        "{%0,%1,%2,%3}, {%4,%5,%6,%7}, {%8,%9}, {%0,%1,%2,%3};"
        : "+f"(d.x), "+f"(d.y), "+f"(d.z), "+f"(d.w)
        : "r"(a[0]), "r"(a[1]), "r"(a[2]), "r"(a[3]), "r"(b0), "r"(b1));
}

__device__ __forceinline__ float sigf(float x) { return 1.0f / (1.0f + __expf(-x)); }

__device__ __forceinline__ uint32_t smem_u32(const void* p) {
    uint32_t a;
    asm("{ .reg .u64 t; cvta.to.shared.u64 t, %1; cvt.u32.u64 %0, t; }"
        : "=r"(a) : "l"(p));
    return a;
}
__device__ __forceinline__ void mbar_init(uint32_t m, uint32_t cnt) {
    asm volatile("mbarrier.init.shared.b64 [%0], %1;" :: "r"(m), "r"(cnt) : "memory");
}
__device__ __forceinline__ void mbar_expect_tx(uint32_t m, uint32_t bytes) {
    asm volatile("mbarrier.arrive.expect_tx.shared.b64 _, [%0], %1;"
                 :: "r"(m), "r"(bytes) : "memory");
}
__device__ __forceinline__ void mbar_wait(uint32_t m, uint32_t phase) {
    asm volatile(
        "{\n\t"
        ".reg .pred P;\n\t"
        "WAIT_%=:\n\t"
        "mbarrier.try_wait.parity.acquire.cta.shared::cta.b64 P, [%0], %1, 0x989680;\n\t"
        "@P bra.uni DONE_%=;\n\t"
        "bra.uni WAIT_%=;\n\t"
        "DONE_%=:\n\t"
        "}"
        :: "r"(m), "r"(phase) : "memory");
}
__device__ __forceinline__ uint32_t mapa_u32(uint32_t addr, uint32_t rank) {
    uint32_t r;
    asm("mapa.shared::cluster.u32 %0, %1, %2;" : "=r"(r) : "r"(addr), "r"(rank));
    return r;
}
__device__ __forceinline__ void st_async_u32(uint32_t raddr, uint32_t val,
                                             uint32_t rmbar) {
    asm volatile(
        "st.async.shared::cluster.mbarrier::complete_tx::bytes.b32 [%0], %1, [%2];"
        :: "r"(raddr), "r"(val), "r"(rmbar) : "memory");
}

// fused persistent PLSTM, DSMEM cluster exchange.
// 128 CTAs = 16 clusters (groups of 8 batches) x 8 slices (32 h-units).
// D[128 gates, 8 b] = [U^T|W^T][128,384] @ [h; x_t][384,8], bf16x3 mma.
// h exchange: producers st.async pre-permuted hi/lo words directly into all
// 8 cluster CTAs' SMEM, double-buffered, mbarrier complete_tx signaling.
__global__ __launch_bounds__(256, 1) __cluster_dims__(8, 1, 1)
void plstm_rec(
    const float* __restrict__ X, const float* __restrict__ U,
    const float* __restrict__ Wm, const float* __restrict__ bias,
    const float* __restrict__ ts, const float* __restrict__ Per,
    const float* __restrict__ Shf, const float* __restrict__ Oe,
    float* __restrict__ out, int writeTails) {
    __shared__ __align__(16) uint32_t Hh[2][8][HPITCH];   // h hi pairs (recv)
    __shared__ __align__(16) uint32_t Hl[2][8][HPITCH];   // h lo pairs (recv)
    __shared__ __align__(16) uint32_t Xh[8][XPITCH];      // x hi pairs (local)
    __shared__ __align__(16) uint32_t Xl[8][XPITCH];      // x lo pairs (local)
    __shared__ __align__(16) float d_sm[128 * 10];
    __shared__ __align__(8) uint64_t mbars[2];

    const int tid = threadIdx.x;
    const int lane = tid & 31;
    const int w = tid >> 5;
    const int gp = lane >> 2;
    const int t4 = lane & 3;
    const int grp = blockIdx.x >> 3;
    const int hslc = blockIdx.x & 7;          // == cluster_ctarank
    const int bg0 = grp * 8;
    const int hs = hslc * 32;
    const int ob = w;
    const int oj = lane;
    const int jg = hs + oj;

    const uint32_t mb = smem_u32(&mbars[0]);  // mbars[k] at mb + 8k
    const uint32_t hhB0 = smem_u32(&Hh[0][0][0]);
    const uint32_t hhB1 = smem_u32(&Hh[1][0][0]);
    const uint32_t hlB0 = smem_u32(&Hl[0][0][0]);
    const uint32_t hlB1 = smem_u32(&Hl[1][0][0]);
    // this thread's send offset: row ob, pair 16*hslc + (oj>>1), hi/lo by parity
    const uint32_t sendOff = (uint32_t)(ob * HPITCH + 16 * hslc + (oj >> 1)) * 4u;
    const uint32_t sbase0 = ((lane & 1) ? hlB0 : hhB0) + sendOff;
    const uint32_t sbase1 = ((lane & 1) ? hlB1 : hhB1) + sendOff;

    const float pv = fabsf(Per[jg]);
    const float sv = Shf[jg];
    const float oe = fabsf(Oe[jg]);
    const float on_end = oe * pv;
    const float on_mid = (oe * 0.5f) * pv;

    const float Bi = bias[jg], Bf = bias[256 + jg];
    const float Bg = bias[512 + jg], Bo = bias[768 + jg];

    // one-time: preload A^T fragments, q 0..15 = U, q 16..23 = W (hi/lo).
    uint32_t Ahi[24][4], Alo[24][4];
    {
        const int gblk = w >> 1;
        const int u0 = (w & 1) * 16;
        const int gc0 = gblk * 256 + hs + u0 + gp;
        const int gc1 = gc0 + 8;
#pragma unroll
        for (int q = 0; q < 16; q++) {
            const int k0 = q * 16 + 2 * t4;
            float x, y;
            x = U[(size_t)k0 * 1024 + gc0];       y = U[(size_t)(k0 + 1) * 1024 + gc0];
            split_pack(x, y, Ahi[q][0], Alo[q][0]);
            x = U[(size_t)k0 * 1024 + gc1];       y = U[(size_t)(k0 + 1) * 1024 + gc1];
            split_pack(x, y, Ahi[q][1], Alo[q][1]);
            x = U[(size_t)(k0 + 8) * 1024 + gc0]; y = U[(size_t)(k0 + 9) * 1024 + gc0];
            split_pack(x, y, Ahi[q][2], Alo[q][2]);
            x = U[(size_t)(k0 + 8) * 1024 + gc1]; y = U[(size_t)(k0 + 9) * 1024 + gc1];
            split_pack(x, y, Ahi[q][3], Alo[q][3]);
        }
#pragma unroll
        for (int q2 = 0; q2 < 8; q2++) {
            const int q = 16 + q2;
            const int k0 = q2 * 16 + 2 * t4;
            float x, y;
            x = Wm[(size_t)k0 * 1024 + gc0];       y = Wm[(size_t)(k0 + 1) * 1024 + gc0];
            split_pack(x, y, Ahi[q][0], Alo[q][0]);
            x = Wm[(size_t)k0 * 1024 + gc1];       y = Wm[(size_t)(k0 + 1) * 1024 + gc1];
            split_pack(x, y, Ahi[q][1], Alo[q][1]);
            x = Wm[(size_t)(k0 + 8) * 1024 + gc0]; y = Wm[(size_t)(k0 + 9) * 1024 + gc0];
            split_pack(x, y, Ahi[q][2], Alo[q][2]);
            x = Wm[(size_t)(k0 + 8) * 1024 + gc1]; y = Wm[(size_t)(k0 + 9) * 1024 + gc1];
            split_pack(x, y, Ahi[q][3], Alo[q][3]);
        }
    }

    // init: mbarriers (count=1, armed for phase 0) + zero buf0 h region
    if (tid == 0) {
        mbar_init(mb, 1);
        mbar_init(mb + 8, 1);
        mbar_expect_tx(mb, TXBYTES);
        mbar_expect_tx(mb + 8, TXBYTES);
    }
    for (int i = tid; i < 8 * HPITCH; i += 256) {
        (&Hh[0][0][0])[i] = 0u;
        (&Hl[0][0][0])[i] = 0u;
    }
    __syncthreads();
    asm volatile("barrier.cluster.arrive.aligned;" ::: "memory");
    asm volatile("barrier.cluster.wait.aligned;" ::: "memory");

    float ccar = 0.f, hcar = 0.f;
    const float* tsrow = ts + (size_t)(bg0 + ob) * S_;
    float tt = tsrow[0];

    const float* xbase = X + (size_t)(bg0 + w) * S_ * I_ + lane * 4;
    float4 xv = *reinterpret_cast<const float4*>(xbase);   // x(0)

    // prologue: stage x(0), compute xW(0)
    float4 Da, Db, Dc;
    {
        uint32_t h0, l0, h1, l1;
        split_pack(xv.x, xv.y, h0, l0);
        split_pack(xv.z, xv.w, h1, l1);
        const int dst = w * XPITCH + lane * 2;
        (&Xh[0][0])[dst] = h0; (&Xh[0][0])[dst + 1] = h1;
        (&Xl[0][0])[dst] = l0; (&Xl[0][0])[dst + 1] = l1;
    }
    __syncthreads();
    Da = make_float4(0.f, 0.f, 0.f, 0.f);
    Db = make_float4(0.f, 0.f, 0.f, 0.f);
    Dc = make_float4(0.f, 0.f, 0.f, 0.f);
#pragma unroll
    for (int q2 = 0; q2 < 8; q2++) {
        const int base = gp * XPITCH + q2 * 8 + t4;
        uint32_t bh0 = (&Xh[0][0])[base], bh1 = (&Xh[0][0])[base + 4];
        uint32_t bl0 = (&Xl[0][0])[base], bl1 = (&Xl[0][0])[base + 4];
        mma_bf16(Da, Ahi[16 + q2], bh0, bh1);
        mma_bf16(Db, Ahi[16 + q2], bl0, bl1);
        mma_bf16(Dc, Alo[16 + q2], bh0, bh1);
    }
    xv = *reinterpret_cast<const float4*>(xbase + I_);      // x(1)

    int ph0 = 0, ph1 = 0;

    for (int s = 0; s < S_; s++) {
        const int cur = s & 1, nxt = cur ^ 1;

        // ---- wait for h(s) (buf cur); re-arm for its next use ----
        if (s > 0) {
            const uint32_t m = mb + (uint32_t)cur * 8u;
            if (cur) { mbar_wait(m, ph1); }
            else     { mbar_wait(m, ph0); }
            if (tid == 0) mbar_expect_tx(m, TXBYTES);
            if (cur) ph1 ^= 1; else ph0 ^= 1;
        }

        // ---- h*U MMA (q 0..15) onto xW(s) accumulators ----
        {
            const uint32_t* hh = &Hh[cur][0][0];
            const uint32_t* hl = &Hl[cur][0][0];
#pragma unroll
            for (int q = 0; q < 16; q++) {
                const int base = gp * HPITCH + q * 8 + t4;
                uint32_t bh0 = hh[base], bh1 = hh[base + 4];
                uint32_t bl0 = hl[base], bl1 = hl[base + 4];
                mma_bf16(Da, Ahi[q], bh0, bh1);
                mma_bf16(Db, Ahi[q], bl0, bl1);
                mma_bf16(Dc, Alo[q], bh0, bh1);
            }
        }
        float4 D = make_float4(Da.x + Db.x + Dc.x, Da.y + Db.y + Dc.y,
                               Da.z + Db.z + Dc.z, Da.w + Db.w + Dc.w);
        {
            const int r0 = 16 * w + gp;
            d_sm[r0 * 10 + 2 * t4] = D.x;
            d_sm[r0 * 10 + 2 * t4 + 1] = D.y;
            d_sm[(r0 + 8) * 10 + 2 * t4] = D.z;
            d_sm[(r0 + 8) * 10 + 2 * t4 + 1] = D.w;
        }
        __syncthreads();                         // sync B: D scattered

        // ---- cell ----
        float p0 = d_sm[(0 * 32 + oj) * 10 + ob];
        float p1 = d_sm[(1 * 32 + oj) * 10 + ob];
        float p2 = d_sm[(2 * 32 + oj) * 10 + ob];
        float p3 = d_sm[(3 * 32 + oj) * 10 + ob];

        float it = sigf(Bi + p0);
        float ft = sigf(Bf + p1);
        float gt = tanhf(Bg + p2);
        float ot = sigf(Bo + p3);
        float cn = ft * ccar + it * gt;
        float hn = ot * tanhf(cn);

        float ic = fmodf(tt + sv, pv);
        float mask;
        if (ic <= on_mid)      mask = ic / on_mid;
        else if (ic <= on_end) mask = (on_end - ic) / on_mid;
        else                   mask = OFF_SLOPE * (ic / pv);

        ccar = mask * cn + (1.f - mask) * ccar;
        float h2 = mask * hn + (1.f - mask) * hcar;
        hcar = h2;

        // ---- push h(s+1) into all 8 cluster CTAs (pre-permuted hi/lo) ----
        if (s + 1 < S_) {
            __nv_bfloat16 hb = __float2bfloat16(h2);
            __nv_bfloat16 lb = __float2bfloat16(h2 - __bfloat162float(hb));
            uint32_t packed = (uint32_t)__bfloat16_as_ushort(hb) |
                              ((uint32_t)__bfloat16_as_ushort(lb) << 16);
            uint32_t op = __shfl_xor_sync(0xffffffffu, packed, 1);
            uint32_t word = (lane & 1) ? __byte_perm(op, packed, 0x7632)
                                       : __byte_perm(packed, op, 0x5410);
            const uint32_t la = nxt ? sbase1 : sbase0;
            const uint32_t lm = mb + (uint32_t)nxt * 8u;
#pragma unroll
            for (uint32_t r = 0; r < 8; r++) {
                uint32_t ra = mapa_u32(la, r);
                uint32_t rm = mapa_u32(lm, r);
                st_async_u32(ra, word, rm);
            }
        }

        // ==== barrier-hiding window ====
        out[((size_t)(bg0 + ob) * S_ + s) * H_ + jg] = h2;

        if (s + 1 < S_) {
            // stage x(s+1)
            uint32_t h0, l0, h1, l1;
            split_pack(xv.x, xv.y, h0, l0);
            split_pack(xv.z, xv.w, h1, l1);
            const int dst = w * XPITCH + lane * 2;
            (&Xh[0][0])[dst] = h0; (&Xh[0][0])[dst + 1] = h1;
            (&Xl[0][0])[dst] = l0; (&Xl[0][0])[dst + 1] = l1;
            __syncthreads();                     // sync D: x(s+1) staged

            // xW(s+1) MMA into fresh accumulators
            Da = make_float4(0.f, 0.f, 0.f, 0.f);
            Db = make_float4(0.f, 0.f, 0.f, 0.f);
            Dc = make_float4(0.f, 0.f, 0.f, 0.f);
#pragma unroll
            for (int q2 = 0; q2 < 8; q2++) {
                const int base = gp * XPITCH + q2 * 8 + t4;
                uint32_t bh0 = (&Xh[0][0])[base], bh1 = (&Xh[0][0])[base + 4];
                uint32_t bl0 = (&Xl[0][0])[base], bl1 = (&Xl[0][0])[base + 4];
                mma_bf16(Da, Ahi[16 + q2], bh0, bh1);
                mma_bf16(Db, Ahi[16 + q2], bl0, bl1);
                mma_bf16(Dc, Alo[16 + q2], bh0, bh1);
            }
            if (s + 2 < S_)
                xv = *reinterpret_cast<const float4*>(xbase + (size_t)(s + 2) * I_);
            tt = tsrow[s + 1];
        }
    }

    if (writeTails) {
        const size_t baseT = (size_t)B_ * S_ * H_;
        out[baseT + (size_t)(bg0 + ob) * H_ + jg] = hcar;                    // h_T
        out[baseT + (size_t)B_ * H_ + (size_t)(bg0 + ob) * H_ + jg] = ccar;  // c_T
    }

    // no CTA may exit while peers could still be mid-flight on DSMEM
    asm volatile("barrier.cluster.arrive.aligned;" ::: "memory");
    asm volatile("barrier.cluster.wait.aligned;" ::: "memory");
}

// ---------------- launch ----------------
extern "C" void kernel_launch(void* const* d_in, const int* in_sizes, int n_in,
                              void* d_out, int out_size) {
    const float* x    = (const float*)d_in[0];
    const float* ts   = (const float*)d_in[1];
    const float* W    = (const float*)d_in[2];
    const float* U    = (const float*)d_in[3];
    const float* bias = (const float*)d_in[4];
    const float* Per  = (const float*)d_in[5];
    const float* Shf  = (const float*)d_in[6];
    const float* Oe   = (const float*)d_in[7];
    float* out = (float*)d_out;

    const long long need = (long long)B_ * S_ * H_ + 2LL * B_ * H_;
    int writeTails = ((long long)out_size >= need) ? 1 : 0;
    plstm_rec<<<128, 256>>>(x, U, W, bias, ts, Per, Shf, Oe, out, writeTails);
}

// round 14
// speedup vs baseline: 1.1330x; 1.1330x over previous
#include <cuda_runtime.h>
#include <cuda_bf16.h>
#include <cstdint>

#define B_   128
#define S_   1024
#define I_   128
#define H_   256
#define OFF_SLOPE 0.001f
#define RPITCH 200   // h row pitch in u32 pairs (=8 mod 32: conflict-free LDS.64)
#define XPITCH 72    // x row pitch in u32 pairs (=8 mod 32)
#define PERM(jj) ((((jj) & 3) << 1) | ((jj) >> 2))

// ---------------- device scratch (static, no allocations) ----------------
__device__ __align__(16) unsigned g_hpack[2][B_ * H_];     // packed (bf16 hi|lo<<16)
__device__ __align__(128) unsigned g_flag[16][8][8][32];   // [grp][slice][warp], own line

__device__ __forceinline__ void split_pack(float x, float y,
                                           uint32_t& hi, uint32_t& lo) {
    __nv_bfloat16 hx = __float2bfloat16(x);
    __nv_bfloat16 hy = __float2bfloat16(y);
    __nv_bfloat16 lx = __float2bfloat16(x - __bfloat162float(hx));
    __nv_bfloat16 ly = __float2bfloat16(y - __bfloat162float(hy));
    hi = (uint32_t)__bfloat16_as_ushort(hx) | ((uint32_t)__bfloat16_as_ushort(hy) << 16);
    lo = (uint32_t)__bfloat16_as_ushort(lx) | ((uint32_t)__bfloat16_as_ushort(ly) << 16);
}

__device__ __forceinline__ void mma_bf16(float4& d, const uint32_t* a,
                                         uint32_t b0, uint32_t b1) {
    asm volatile(
        "mma.sync.aligned.m16n8k16.row.col.f32.bf16.bf16.f32 "
        "{%0,%1,%2,%3}, {%4,%5,%6,%7}, {%8,%9}, {%0,%1,%2,%3};"
        : "+f"(d.x), "+f"(d.y), "+f"(d.z), "+f"(d.w)
        : "r"(a[0]), "r"(a[1]), "r"(a[2]), "r"(a[3]), "r"(b0), "r"(b1));
}

// ---------------- init: zero flags ----------------
__global__ void init_k() {
    unsigned t = blockIdx.x * blockDim.x + threadIdx.x;
    for (unsigned i = t; i < 16u * 8u * 8u * 32u; i += gridDim.x * blockDim.x)
        ((unsigned*)g_flag)[i] = 0u;
}

__device__ __forceinline__ float sigf(float x) { return 1.0f / (1.0f + __expf(-x)); }

__device__ __forceinline__ unsigned ld_acq(const unsigned* p) {
    unsigned v;
    asm volatile("ld.global.acquire.gpu.u32 %0, [%1];" : "=r"(v) : "l"(p) : "memory");
    return v;
}
__device__ __forceinline__ void st_release(unsigned* p, unsigned v) {
    asm volatile("st.release.gpu.global.u32 [%0], %1;" :: "l"(p), "r"(v) : "memory");
}
__device__ __forceinline__ uint2 ldcg_u2(const uint2* p) {
    uint2 v;
    asm volatile("ld.global.cg.v2.u32 {%0,%1}, [%2];"
                 : "=r"(v.x), "=r"(v.y) : "l"(p));
    return v;
}

// fused persistent PLSTM: 128 CTAs = 16 groups (8 batches) x 8 slices.
// D[128 gates, 8 b] = [U^T|W^T][128,384] @ [h; x_t][384,8], bf16x3 mma.
// Exchange: per-warp L2 flags (producer warp releases its own batch's flag
// immediately after publish); xW(s+1) + out-store + mask(s+1) fill the
// flag-propagation window. LDS.64 B-fragments via pair permutation.
__global__ __launch_bounds__(256, 1) void plstm_rec(
    const float* __restrict__ X, const float* __restrict__ U,
    const float* __restrict__ Wm, const float* __restrict__ bias,
    const float* __restrict__ ts, const float* __restrict__ Per,
    const float* __restrict__ Shf, const float* __restrict__ Oe,
    float* __restrict__ out, int writeTails) {
    __shared__ __align__(16) uint32_t Hh[2][8][RPITCH];   // h hi pairs
    __shared__ __align__(16) uint32_t Hl[2][8][RPITCH];   // h lo pairs
    __shared__ __align__(16) uint32_t Xh[2][8][XPITCH];   // x hi pairs
    __shared__ __align__(16) uint32_t Xl[2][8][XPITCH];   // x lo pairs
    __shared__ __align__(16) float d_sm[128 * 10];

    const int tid = threadIdx.x;
    const int lane = tid & 31;
    const int w = tid >> 5;
    const int gp = lane >> 2;
    const int t4 = lane & 3;
    const int grp = blockIdx.x >> 3;
    const int hslc = blockIdx.x & 7;
    const int bg0 = grp * 8;
    const int hs = hslc * 32;
    const int ob = w;
    const int oj = lane;
    const int jg = hs + oj;

    const float pv = fabsf(Per[jg]);
    const float sv = Shf[jg];
    const float oe = fabsf(Oe[jg]);
    const float on_end = oe * pv;
    const float on_mid = (oe * 0.5f) * pv;

    const float Bi = bias[jg], Bf = bias[256 + jg];
    const float Bg = bias[512 + jg], Bo = bias[768 + jg];

    // one-time: preload A^T fragments, q 0..15 = U, q 16..23 = W (hi/lo).
    uint32_t Ahi[24][4], Alo[24][4];
    {
        const int gblk = w >> 1;
        const int u0 = (w & 1) * 16;
        const int gc0 = gblk * 256 + hs + u0 + gp;
        const int gc1 = gc0 + 8;
#pragma unroll
        for (int q = 0; q < 16; q++) {
            const int k0 = q * 16 + 2 * t4;
            float x, y;
            x = U[(size_t)k0 * 1024 + gc0];       y = U[(size_t)(k0 + 1) * 1024 + gc0];
            split_pack(x, y, Ahi[q][0], Alo[q][0]);
            x = U[(size_t)k0 * 1024 + gc1];       y = U[(size_t)(k0 + 1) * 1024 + gc1];
            split_pack(x, y, Ahi[q][1], Alo[q][1]);
            x = U[(size_t)(k0 + 8) * 1024 + gc0]; y = U[(size_t)(k0 + 9) * 1024 + gc0];
            split_pack(x, y, Ahi[q][2], Alo[q][2]);
            x = U[(size_t)(k0 + 8) * 1024 + gc1]; y = U[(size_t)(k0 + 9) * 1024 + gc1];
            split_pack(x, y, Ahi[q][3], Alo[q][3]);
        }
#pragma unroll
        for (int q2 = 0; q2 < 8; q2++) {
            const int q = 16 + q2;
            const int k0 = q2 * 16 + 2 * t4;
            float x, y;
            x = Wm[(size_t)k0 * 1024 + gc0];       y = Wm[(size_t)(k0 + 1) * 1024 + gc0];
            split_pack(x, y, Ahi[q][0], Alo[q][0]);
            x = Wm[(size_t)k0 * 1024 + gc1];       y = Wm[(size_t)(k0 + 1) * 1024 + gc1];
            split_pack(x, y, Ahi[q][1], Alo[q][1]);
            x = Wm[(size_t)(k0 + 8) * 1024 + gc0]; y = Wm[(size_t)(k0 + 9) * 1024 + gc0];
            split_pack(x, y, Ahi[q][2], Alo[q][2]);
            x = Wm[(size_t)(k0 + 8) * 1024 + gc1]; y = Wm[(size_t)(k0 + 9) * 1024 + gc1];
            split_pack(x, y, Ahi[q][3], Alo[q][3]);
        }
    }

    // zero h buffer 0 (h(0) = 0); buffer 1 fully overwritten at s=1
    for (int i = tid; i < 8 * RPITCH; i += 256) {
        (&Hh[0][0][0])[i] = 0u;
        (&Hl[0][0][0])[i] = 0u;
    }

    float ccar = 0.f, hcar = 0.f;
    const float* tsrow = ts + (size_t)(bg0 + ob) * S_;

    // mask(0)
    float mcur;
    {
        float ic = fmodf(tsrow[0] + sv, pv);
        if (ic <= on_mid)      mcur = ic / on_mid;
        else if (ic <= on_end) mcur = (on_end - ic) / on_mid;
        else                   mcur = OFF_SLOPE * (ic / pv);
    }

    const float* xbase = X + (size_t)(bg0 + w) * S_ * I_ + lane * 4;
    float4 xv = *reinterpret_cast<const float4*>(xbase);   // x(0)

    // prologue: stage x(0) into Xh[0] (permuted), compute xW(0)
    float4 Da, Db, Dc;
    {
        uint32_t h0, l0, h1, l1;
        split_pack(xv.x, xv.y, h0, l0);
        split_pack(xv.z, xv.w, h1, l1);
        const int j0 = 2 * lane;
        const int q0 = j0 >> 3, jj0 = j0 & 7;
        const int d0 = w * XPITCH + q0 * 8 + PERM(jj0);
        const int d1 = w * XPITCH + q0 * 8 + PERM(jj0 + 1);
        Xh[0][0][d0] = h0; Xh[0][0][d1] = h1;
        Xl[0][0][d0] = l0; Xl[0][0][d1] = l1;
    }
    __syncthreads();
    Da = make_float4(0.f, 0.f, 0.f, 0.f);
    Db = make_float4(0.f, 0.f, 0.f, 0.f);
    Dc = make_float4(0.f, 0.f, 0.f, 0.f);
    {
        const uint2* xh2 = reinterpret_cast<const uint2*>(&Xh[0][0][0]);
        const uint2* xl2 = reinterpret_cast<const uint2*>(&Xl[0][0][0]);
#pragma unroll
        for (int q2 = 0; q2 < 8; q2++) {
            uint2 bh = xh2[gp * (XPITCH / 2) + q2 * 4 + t4];
            uint2 bl = xl2[gp * (XPITCH / 2) + q2 * 4 + t4];
            mma_bf16(Da, Ahi[16 + q2], bh.x, bh.y);
            mma_bf16(Db, Ahi[16 + q2], bl.x, bl.y);
            mma_bf16(Dc, Alo[16 + q2], bh.x, bh.y);
        }
    }
    xv = *reinterpret_cast<const float4*>(xbase + I_);      // x(1)

    for (int s = 0; s < S_; s++) {
        const int cur = s & 1, nxt = cur ^ 1;

        // ---- per-warp poll (8 flags, one per source warp) + stage h(s) ----
        if (s > 0) {
            if (lane < 8) {
                const unsigned* f = &g_flag[grp][w][lane][0];
                while (ld_acq(f) < (unsigned)s) {}
            }
            __syncwarp();
            const int p = lane & 15;
            const int poff = (2 * w + (p >> 3)) * 8 + PERM(p & 7);
#pragma unroll
            for (int i = 0; i < 4; i++) {
                const int b = 2 * i + (lane >> 4);
                uint2 u = ldcg_u2(reinterpret_cast<const uint2*>(
                    &g_hpack[cur][(bg0 + b) * H_ + 32 * w + 2 * p]));
                const int dst = b * RPITCH + poff;
                Hh[cur][0][dst] = __byte_perm(u.x, u.y, 0x5410);
                Hl[cur][0][dst] = __byte_perm(u.x, u.y, 0x7632);
            }
        }
        __syncthreads();                         // sync A: h(s) staged

        // ---- h*U MMA (q 0..15) onto xW(s) accumulators (LDS.64) ----
        {
            const uint2* hh2 = reinterpret_cast<const uint2*>(&Hh[cur][0][0]);
            const uint2* hl2 = reinterpret_cast<const uint2*>(&Hl[cur][0][0]);
#pragma unroll
            for (int q = 0; q < 16; q++) {
                uint2 bh = hh2[gp * (RPITCH / 2) + q * 4 + t4];
                uint2 bl = hl2[gp * (RPITCH / 2) + q * 4 + t4];
                mma_bf16(Da, Ahi[q], bh.x, bh.y);
                mma_bf16(Db, Ahi[q], bl.x, bl.y);
                mma_bf16(Dc, Alo[q], bh.x, bh.y);
            }
        }
        float4 D = make_float4(Da.x + Db.x + Dc.x, Da.y + Db.y + Dc.y,
                               Da.z + Db.z + Dc.z, Da.w + Db.w + Dc.w);
        {
            const int r0 = 16 * w + gp;
            d_sm[r0 * 10 + 2 * t4] = D.x;
            d_sm[r0 * 10 + 2 * t4 + 1] = D.y;
            d_sm[(r0 + 8) * 10 + 2 * t4] = D.z;
            d_sm[(r0 + 8) * 10 + 2 * t4 + 1] = D.w;
        }

        // ---- stage x(s+1) into Xh[nxt] (covered by sync B) ----
        if (s + 1 < S_) {
            uint32_t h0, l0, h1, l1;
            split_pack(xv.x, xv.y, h0, l0);
            split_pack(xv.z, xv.w, h1, l1);
            const int j0 = 2 * lane;
            const int q0 = j0 >> 3, jj0 = j0 & 7;
            const int d0 = w * XPITCH + q0 * 8 + PERM(jj0);
            const int d1 = w * XPITCH + q0 * 8 + PERM(jj0 + 1);
            Xh[nxt][0][d0] = h0; Xh[nxt][0][d1] = h1;
            Xl[nxt][0][d0] = l0; Xl[nxt][0][d1] = l1;
        }
        __syncthreads();                         // sync B: D + x(s+1) ready

        // ---- cell (mask precomputed) ----
        float p0 = d_sm[(0 * 32 + oj) * 10 + ob];
        float p1 = d_sm[(1 * 32 + oj) * 10 + ob];
        float p2 = d_sm[(2 * 32 + oj) * 10 + ob];
        float p3 = d_sm[(3 * 32 + oj) * 10 + ob];

        float it = sigf(Bi + p0);
        float ft = sigf(Bf + p1);
        float gt = tanhf(Bg + p2);
        float ot = sigf(Bo + p3);
        float cn = ft * ccar + it * gt;
        float hn = ot * tanhf(cn);

        ccar = mcur * cn + (1.f - mcur) * ccar;
        float h2 = mcur * hn + (1.f - mcur) * hcar;
        hcar = h2;

        // ---- publish + per-warp flag release (no CTA sync) ----
        __nv_bfloat16 hb = __float2bfloat16(h2);
        __nv_bfloat16 lb = __float2bfloat16(h2 - __bfloat162float(hb));
        g_hpack[nxt][(bg0 + ob) * H_ + jg] =
            (uint32_t)__bfloat16_as_ushort(hb) |
            ((uint32_t)__bfloat16_as_ushort(lb) << 16);
        __syncwarp();
        if (lane == 0) st_release(&g_flag[grp][hslc][w][0], (unsigned)(s + 1));

        // ==== flag-propagation window ====
        out[((size_t)(bg0 + ob) * S_ + s) * H_ + jg] = h2;

        if (s + 1 < S_) {
            // xW(s+1) MMA into fresh accumulators (reads Xh[nxt], sync-B-covered)
            Da = make_float4(0.f, 0.f, 0.f, 0.f);
            Db = make_float4(0.f, 0.f, 0.f, 0.f);
            Dc = make_float4(0.f, 0.f, 0.f, 0.f);
            const uint2* xh2 = reinterpret_cast<const uint2*>(&Xh[nxt][0][0]);
            const uint2* xl2 = reinterpret_cast<const uint2*>(&Xl[nxt][0][0]);
#pragma unroll
            for (int q2 = 0; q2 < 8; q2++) {
                uint2 bh = xh2[gp * (XPITCH / 2) + q2 * 4 + t4];
                uint2 bl = xl2[gp * (XPITCH / 2) + q2 * 4 + t4];
                mma_bf16(Da, Ahi[16 + q2], bh.x, bh.y);
                mma_bf16(Db, Ahi[16 + q2], bl.x, bl.y);
                mma_bf16(Dc, Alo[16 + q2], bh.x, bh.y);
            }
            if (s + 2 < S_)
                xv = *reinterpret_cast<const float4*>(xbase + (size_t)(s + 2) * I_);
            // mask(s+1)
            float ic = fmodf(tsrow[s + 1] + sv, pv);
            if (ic <= on_mid)      mcur = ic / on_mid;
            else if (ic <= on_end) mcur = (on_end - ic) / on_mid;
            else                   mcur = OFF_SLOPE * (ic / pv);
        }
    }

    if (writeTails) {
        const size_t baseT = (size_t)B_ * S_ * H_;
        out[baseT + (size_t)(bg0 + ob) * H_ + jg] = hcar;                    // h_T
        out[baseT + (size_t)B_ * H_ + (size_t)(bg0 + ob) * H_ + jg] = ccar;  // c_T
    }
}

// ---------------- launch ----------------
extern "C" void kernel_launch(void* const* d_in, const int* in_sizes, int n_in,
                              void* d_out, int out_size) {
    const float* x    = (const float*)d_in[0];
    const float* ts   = (const float*)d_in[1];
    const float* W    = (const float*)d_in[2];
    const float* U    = (const float*)d_in[3];
    const float* bias = (const float*)d_in[4];
    const float* Per  = (const float*)d_in[5];
    const float* Shf  = (const float*)d_in[6];
    const float* Oe   = (const float*)d_in[7];
    float* out = (float*)d_out;

    init_k<<<64, 256>>>();

    const long long need = (long long)B_ * S_ * H_ + 2LL * B_ * H_;
    int writeTails = ((long long)out_size >= need) ? 1 : 0;
    plstm_rec<<<128, 256>>>(x, U, W, bias, ts, Per, Shf, Oe, out, writeTails);
}

// round 16
// speedup vs baseline: 1.2914x; 1.1398x over previous
#include <cuda_runtime.h>
#include <cuda_bf16.h>
#include <cstdint>

#define B_   128
#define S_   1024
#define I_   128
#define H_   256
#define OFF_SLOPE 0.001f
#define RPITCH 196   // SMEM row pitch (u32 pairs): 128 h + 64 x + pad

// ---------------- device scratch (static, no allocations) ----------------
__device__ __align__(16) unsigned g_hpack[2][B_ * H_];  // packed (bf16 hi | lo<<16)
__device__ __align__(128) unsigned g_flag[16][8][32];   // [grp][cta], own 128B line

__device__ __forceinline__ void split_pack(float x, float y,
                                           uint32_t& hi, uint32_t& lo) {
    __nv_bfloat16 hx = __float2bfloat16(x);
    __nv_bfloat16 hy = __float2bfloat16(y);
    __nv_bfloat16 lx = __float2bfloat16(x - __bfloat162float(hx));
    __nv_bfloat16 ly = __float2bfloat16(y - __bfloat162float(hy));
    hi = (uint32_t)__bfloat16_as_ushort(hx) | ((uint32_t)__bfloat16_as_ushort(hy) << 16);
    lo = (uint32_t)__bfloat16_as_ushort(lx) | ((uint32_t)__bfloat16_as_ushort(ly) << 16);
}

__device__ __forceinline__ void mma_bf16(float4& d, const uint32_t* a,
                                         uint32_t b0, uint32_t b1) {
    asm volatile(
        "mma.sync.aligned.m16n8k16.row.col.f32.bf16.bf16.f32 "
        "{%0,%1,%2,%3}, {%4,%5,%6,%7}, {%8,%9}, {%0,%1,%2,%3};"
        : "+f"(d.x), "+f"(d.y), "+f"(d.z), "+f"(d.w)
        : "r"(a[0]), "r"(a[1]), "r"(a[2]), "r"(a[3]), "r"(b0), "r"(b1));
}

// ---------------- init: zero flags + h0 ----------------
__global__ void init_k() {
    unsigned t = blockIdx.x * blockDim.x + threadIdx.x;
    if (t < 16u * 8u * 32u) ((unsigned*)g_flag)[t] = 0u;
    for (unsigned i = t; i < 2u * B_ * H_; i += gridDim.x * blockDim.x)
        ((unsigned*)g_hpack)[i] = 0u;
}

__device__ __forceinline__ float sigf(float x) { return 1.0f / (1.0f + __expf(-x)); }

__device__ __forceinline__ unsigned ld_acq(const unsigned* p) {
    unsigned v;
    asm volatile("ld.global.acquire.gpu.u32 %0, [%1];" : "=r"(v) : "l"(p) : "memory");
    return v;
}
__device__ __forceinline__ void st_release(unsigned* p, unsigned v) {
    asm volatile("st.release.gpu.global.u32 [%0], %1;" :: "l"(p), "r"(v) : "memory");
}
__device__ __forceinline__ uint2 ldcg_u2(const uint2* p) {
    uint2 v;
    asm volatile("ld.global.cg.v2.u32 {%0,%1}, [%2];"
                 : "=r"(v.x), "=r"(v.y) : "l"(p));
    return v;
}

// fused persistent PLSTM: 128 CTAs = 16 groups (8 batches) x 8 slices.
// D[128 gates, 8 b] = [U^T|W^T][128,384] @ [h; x_t][384,8], bf16x3 mma.
// R12 exchange (monotone per-slice flags + ldcg data). Pipeline: xW(s+1)
// + out-store + mask(s+1) fill the flag-propagation window; x(s+1) staged
// pre-syncB (disjoint SMEM region) so no extra barrier is needed.
__global__ __launch_bounds__(256, 1) void plstm_rec(
    const float* __restrict__ X, const float* __restrict__ U,
    const float* __restrict__ Wm, const float* __restrict__ bias,
    const float* __restrict__ ts, const float* __restrict__ Per,
    const float* __restrict__ Shf, const float* __restrict__ Oe,
    float* __restrict__ out, int writeTails) {
    __shared__ __align__(16) uint32_t Hhi[8 * RPITCH];
    __shared__ __align__(16) uint32_t Hlo[8 * RPITCH];
    __shared__ __align__(16) float d_sm[128 * 10];

    const int tid = threadIdx.x;
    const int lane = tid & 31;
    const int w = tid >> 5;
    const int gp = lane >> 2;
    const int t4 = lane & 3;
    const int grp = blockIdx.x >> 3;
    const int hslc = blockIdx.x & 7;
    const int bg0 = grp * 8;
    const int hs = hslc * 32;
    const int ob = w;
    const int oj = lane;
    const int jg = hs + oj;

    const float pv = fabsf(Per[jg]);
    const float sv = Shf[jg];
    const float oe = fabsf(Oe[jg]);
    const float on_end = oe * pv;
    const float on_mid = (oe * 0.5f) * pv;

    const float Bi = bias[jg], Bf = bias[256 + jg];
    const float Bg = bias[512 + jg], Bo = bias[768 + jg];

    // one-time: preload A^T fragments, q 0..15 = U, q 16..23 = W (hi/lo).
    uint32_t Ahi[24][4], Alo[24][4];
    {
        const int gblk = w >> 1;
        const int u0 = (w & 1) * 16;
        const int gc0 = gblk * 256 + hs + u0 + gp;
        const int gc1 = gc0 + 8;
#pragma unroll
        for (int q = 0; q < 16; q++) {
            const int k0 = q * 16 + 2 * t4;
            float x, y;
            x = U[(size_t)k0 * 1024 + gc0];       y = U[(size_t)(k0 + 1) * 1024 + gc0];
            split_pack(x, y, Ahi[q][0], Alo[q][0]);
            x = U[(size_t)k0 * 1024 + gc1];       y = U[(size_t)(k0 + 1) * 1024 + gc1];
            split_pack(x, y, Ahi[q][1], Alo[q][1]);
            x = U[(size_t)(k0 + 8) * 1024 + gc0]; y = U[(size_t)(k0 + 9) * 1024 + gc0];
            split_pack(x, y, Ahi[q][2], Alo[q][2]);
            x = U[(size_t)(k0 + 8) * 1024 + gc1]; y = U[(size_t)(k0 + 9) * 1024 + gc1];
            split_pack(x, y, Ahi[q][3], Alo[q][3]);
        }
#pragma unroll
        for (int q2 = 0; q2 < 8; q2++) {
            const int q = 16 + q2;
            const int k0 = q2 * 16 + 2 * t4;
            float x, y;
            x = Wm[(size_t)k0 * 1024 + gc0];       y = Wm[(size_t)(k0 + 1) * 1024 + gc0];
            split_pack(x, y, Ahi[q][0], Alo[q][0]);
            x = Wm[(size_t)k0 * 1024 + gc1];       y = Wm[(size_t)(k0 + 1) * 1024 + gc1];
            split_pack(x, y, Ahi[q][1], Alo[q][1]);
            x = Wm[(size_t)(k0 + 8) * 1024 + gc0]; y = Wm[(size_t)(k0 + 9) * 1024 + gc0];
            split_pack(x, y, Ahi[q][2], Alo[q][2]);
            x = Wm[(size_t)(k0 + 8) * 1024 + gc1]; y = Wm[(size_t)(k0 + 9) * 1024 + gc1];
            split_pack(x, y, Ahi[q][3], Alo[q][3]);
        }
    }

    float ccar = 0.f, hcar = 0.f;
    const float* tsrow = ts + (size_t)(bg0 + ob) * S_;

    // mask(0) precomputed
    float mcur;
    {
        float ic = fmodf(tsrow[0] + sv, pv);
        if (ic <= on_mid)      mcur = ic / on_mid;
        else if (ic <= on_end) mcur = (on_end - ic) / on_mid;
        else                   mcur = OFF_SLOPE * (ic / pv);
    }

    // x stream: warp w owns batch bg0+w; thread covers 4 consecutive dims
    const float* xbase = X + (size_t)(bg0 + w) * S_ * I_ + lane * 4;
    float4 xv = *reinterpret_cast<const float4*>(xbase);   // x(0)

    // ---- prologue: stage x(0), compute xW(0) into accumulators ----
    float4 Da, Db, Dc;
    {
        uint32_t h0, l0, h1, l1;
        split_pack(xv.x, xv.y, h0, l0);
        split_pack(xv.z, xv.w, h1, l1);
        const int dst = w * RPITCH + 128 + lane * 2;
        Hhi[dst] = h0; Hhi[dst + 1] = h1;
        Hlo[dst] = l0; Hlo[dst + 1] = l1;
    }
    __syncthreads();
    Da = make_float4(0.f, 0.f, 0.f, 0.f);
    Db = make_float4(0.f, 0.f, 0.f, 0.f);
    Dc = make_float4(0.f, 0.f, 0.f, 0.f);
#pragma unroll
    for (int q = 16; q < 24; q++) {
        const int base = gp * RPITCH + q * 8 + t4;
        uint32_t bh0 = Hhi[base], bh1 = Hhi[base + 4];
        uint32_t bl0 = Hlo[base], bl1 = Hlo[base + 4];
        mma_bf16(Da, Ahi[q], bh0, bh1);
        mma_bf16(Db, Ahi[q], bl0, bl1);
        mma_bf16(Dc, Alo[q], bh0, bh1);
    }
    xv = *reinterpret_cast<const float4*>(xbase + I_);      // x(1)

    for (int s = 0; s < S_; s++) {
        const int cur = s & 1, nxt = cur ^ 1;

        // ---- poll producer w's flag for h(s), stage h chunk w ----
        if (s > 0) {
            if (lane == 0) {
                const unsigned tgt = (unsigned)s;
                while (ld_acq(&g_flag[grp][w][0]) < tgt) {}
            }
            __syncwarp();
        }
        {
            const int p = lane & 15;
#pragma unroll
            for (int i = 0; i < 4; i++) {
                const int b = 2 * i + (lane >> 4);
                uint2 u = ldcg_u2(reinterpret_cast<const uint2*>(
                    &g_hpack[cur][(bg0 + b) * H_ + 32 * w + 2 * p]));
                const int dst = b * RPITCH + 16 * w + p;
                Hhi[dst] = __byte_perm(u.x, u.y, 0x5410);
                Hlo[dst] = __byte_perm(u.x, u.y, 0x7632);
            }
        }
        __syncthreads();                         // sync A: h(s) staged

        // ---- h*U MMA (q 0..15), accumulating onto xW(s) ----
#pragma unroll
        for (int q = 0; q < 16; q++) {
            const int base = gp * RPITCH + q * 8 + t4;
            uint32_t bh0 = Hhi[base], bh1 = Hhi[base + 4];
            uint32_t bl0 = Hlo[base], bl1 = Hlo[base + 4];
            mma_bf16(Da, Ahi[q], bh0, bh1);
            mma_bf16(Db, Ahi[q], bl0, bl1);
            mma_bf16(Dc, Alo[q], bh0, bh1);
        }
        float4 D = make_float4(Da.x + Db.x + Dc.x, Da.y + Db.y + Dc.y,
                               Da.z + Db.z + Dc.z, Da.w + Db.w + Dc.w);
        {
            const int r0 = 16 * w + gp;
            d_sm[r0 * 10 + 2 * t4] = D.x;
            d_sm[r0 * 10 + 2 * t4 + 1] = D.y;
            d_sm[(r0 + 8) * 10 + 2 * t4] = D.z;
            d_sm[(r0 + 8) * 10 + 2 * t4 + 1] = D.w;
        }

        // ---- stage x(s+1) pre-syncB (x region pairs 128+, disjoint from h) ----
        if (s + 1 < S_) {
            uint32_t h0, l0, h1, l1;
            split_pack(xv.x, xv.y, h0, l0);
            split_pack(xv.z, xv.w, h1, l1);
            const int dst = w * RPITCH + 128 + lane * 2;
            Hhi[dst] = h0; Hhi[dst + 1] = h1;
            Hlo[dst] = l0; Hlo[dst + 1] = l1;
        }
        __syncthreads();                         // sync B: D + x(s+1) ready

        // ---- cell (mask precomputed) ----
        float p0 = d_sm[(0 * 32 + oj) * 10 + ob];
        float p1 = d_sm[(1 * 32 + oj) * 10 + ob];
        float p2 = d_sm[(2 * 32 + oj) * 10 + ob];
        float p3 = d_sm[(3 * 32 + oj) * 10 + ob];

        float it = sigf(Bi + p0);
        float ft = sigf(Bf + p1);
        float gt = tanhf(Bg + p2);
        float ot = sigf(Bo + p3);
        float cn = ft * ccar + it * gt;
        float hn = ot * tanhf(cn);

        ccar = mcur * cn + (1.f - mcur) * ccar;
        float h2 = mcur * hn + (1.f - mcur) * hcar;
        hcar = h2;

        // publish packed h
        __nv_bfloat16 hb = __float2bfloat16(h2);
        __nv_bfloat16 lb = __float2bfloat16(h2 - __bfloat162float(hb));
        g_hpack[nxt][(bg0 + ob) * H_ + jg] =
            (uint32_t)__bfloat16_as_ushort(hb) |
            ((uint32_t)__bfloat16_as_ushort(lb) << 16);

        __syncthreads();                         // sync C: publishes done
        if (tid == 0) st_release(&g_flag[grp][hslc][0], (unsigned)(s + 1));

        // ==== flag-propagation window: work not needing h(s+1) ====
        out[((size_t)(bg0 + ob) * S_ + s) * H_ + jg] = h2;

        if (s + 1 < S_) {
            // xW(s+1) MMA into fresh accumulators (x staged pre-syncB)
            Da = make_float4(0.f, 0.f, 0.f, 0.f);
            Db = make_float4(0.f, 0.f, 0.f, 0.f);
            Dc = make_float4(0.f, 0.f, 0.f, 0.f);
#pragma unroll
            for (int q = 16; q < 24; q++) {
                const int base = gp * RPITCH + q * 8 + t4;
                uint32_t bh0 = Hhi[base], bh1 = Hhi[base + 4];
                uint32_t bl0 = Hlo[base], bl1 = Hlo[base + 4];
                mma_bf16(Da, Ahi[q], bh0, bh1);
                mma_bf16(Db, Ahi[q], bl0, bl1);
                mma_bf16(Dc, Alo[q], bh0, bh1);
            }
            // prefetch x(s+2); mask(s+1)
            if (s + 2 < S_)
                xv = *reinterpret_cast<const float4*>(xbase + (size_t)(s + 2) * I_);
            float ic = fmodf(tsrow[s + 1] + sv, pv);
            if (ic <= on_mid)      mcur = ic / on_mid;
            else if (ic <= on_end) mcur = (on_end - ic) / on_mid;
            else                   mcur = OFF_SLOPE * (ic / pv);
        }
    }

    if (writeTails) {
        const size_t baseT = (size_t)B_ * S_ * H_;
        out[baseT + (size_t)(bg0 + ob) * H_ + jg] = hcar;                    // h_T
        out[baseT + (size_t)B_ * H_ + (size_t)(bg0 + ob) * H_ + jg] = ccar;  // c_T
    }
}

// ---------------- launch ----------------
extern "C" void kernel_launch(void* const* d_in, const int* in_sizes, int n_in,
                              void* d_out, int out_size) {
    const float* x    = (const float*)d_in[0];
    const float* ts   = (const float*)d_in[1];
    const float* W    = (const float*)d_in[2];
    const float* U    = (const float*)d_in[3];
    const float* bias = (const float*)d_in[4];
    const float* Per  = (const float*)d_in[5];
    const float* Shf  = (const float*)d_in[6];
    const float* Oe   = (const float*)d_in[7];
    float* out = (float*)d_out;

    init_k<<<64, 256>>>();

    const long long need = (long long)B_ * S_ * H_ + 2LL * B_ * H_;
    int writeTails = ((long long)out_size >= need) ? 1 : 0;
    plstm_rec<<<128, 256>>>(x, U, W, bias, ts, Per, Shf, Oe, out, writeTails);
}